// round 3
// baseline (speedup 1.0000x reference)
#include <cuda_runtime.h>

typedef unsigned long long u64;

#define TPB   256
#define NCOL  4096
#define VPT   16      // values per thread
#define NPAIR 8
#define NWARP 8
#define KITER 16
#define EPSF  1.1754943508222875e-38f

// ---- packed f32x2 helpers (ptxas never auto-fuses these from C++) ----
__device__ __forceinline__ u64 pk2(float a, float b) {
    u64 r; asm("mov.b64 %0,{%1,%2};" : "=l"(r) : "f"(a), "f"(b)); return r;
}
__device__ __forceinline__ void upk2(u64 v, float& a, float& b) {
    asm("mov.b64 {%0,%1},%2;" : "=f"(a), "=f"(b) : "l"(v));
}
__device__ __forceinline__ u64 mul2(u64 a, u64 b) {
    u64 d; asm("mul.rn.f32x2 %0,%1,%2;" : "=l"(d) : "l"(a), "l"(b)); return d;
}
__device__ __forceinline__ u64 add2(u64 a, u64 b) {
    u64 d; asm("add.rn.f32x2 %0,%1,%2;" : "=l"(d) : "l"(a), "l"(b)); return d;
}
__device__ __forceinline__ u64 fma2(u64 a, u64 b, u64 c) {
    u64 d; asm("fma.rn.f32x2 %0,%1,%2,%3;" : "=l"(d) : "l"(a), "l"(b), "l"(c)); return d;
}
__device__ __forceinline__ float rcpf(float x) {
    float r; asm("rcp.approx.f32 %0,%1;" : "=f"(r) : "f"(x)); return r;
}

// One CTA per row of 4096. w = exp(s - max) kept in registers (8 f32x2 pairs),
// khot accumulated in registers. Per iteration: block-sum(w) -> onehot = w/S,
// khot += onehot, w *= max(1 - onehot, EPS). Algebraically identical to the
// reference's  s += log(mask); softmax(s)  recurrence, with zero per-iteration
// log/exp.
__global__ __launch_bounds__(TPB, 4) void subset_op_kernel(
    const float* __restrict__ scores, const float* __restrict__ g,
    float* __restrict__ out)
{
    __shared__ float red_max[NWARP];
    __shared__ float red_sum[2][NWARP];

    const int tid  = threadIdx.x;
    const int lane = tid & 31;
    const int wid  = tid >> 5;
    const size_t base = (size_t)blockIdx.x * NCOL;

    const float4* sc4 = reinterpret_cast<const float4*>(scores + base);
    const float4* g4  = reinterpret_cast<const float4*>(g + base);

    // ---- load + perturb: s = scores + g (coalesced float4) ----
    float s[VPT];
    #pragma unroll
    for (int j = 0; j < 4; j++) {
        float4 a = sc4[j * TPB + tid];
        float4 b = g4 [j * TPB + tid];
        s[4*j+0] = a.x + b.x; s[4*j+1] = a.y + b.y;
        s[4*j+2] = a.z + b.z; s[4*j+3] = a.w + b.w;
    }

    // ---- block max (one-time) ----
    float m = s[0];
    #pragma unroll
    for (int i = 1; i < VPT; i++) m = fmaxf(m, s[i]);
    #pragma unroll
    for (int o = 16; o > 0; o >>= 1)
        m = fmaxf(m, __shfl_xor_sync(0xffffffffu, m, o));
    if (lane == 0) red_max[wid] = m;
    __syncthreads();
    #pragma unroll
    for (int j = 0; j < NWARP; j++) m = fmaxf(m, red_max[j]);   // broadcast reads, all threads identical

    // ---- w = exp(s - m): the ONLY transcendental in the kernel ----
    u64 w2[NPAIR], k2[NPAIR];
    #pragma unroll
    for (int p = 0; p < NPAIR; p++) {
        w2[p] = pk2(__expf(s[2*p] - m), __expf(s[2*p+1] - m));
        k2[p] = pk2(0.f, 0.f);
    }

    const u64 ONE2  = pk2( 1.f,  1.f);
    const u64 NONE2 = pk2(-1.f, -1.f);

    // ---- 16 iterations, 1 barrier each (parity double-buffered smem) ----
    for (int it = 0; it < KITER; it++) {
        // horizontal sum of this thread's 16 w values (packed tree)
        u64 a0 = add2(w2[0], w2[1]);
        u64 a1 = add2(w2[2], w2[3]);
        u64 a2 = add2(w2[4], w2[5]);
        u64 a3 = add2(w2[6], w2[7]);
        a0 = add2(a0, a1); a2 = add2(a2, a3);
        a0 = add2(a0, a2);
        float lo, hi; upk2(a0, lo, hi);
        float local = lo + hi;

        #pragma unroll
        for (int o = 16; o > 0; o >>= 1)
            local += __shfl_xor_sync(0xffffffffu, local, o);
        if (lane == 0) red_sum[it & 1][wid] = local;
        __syncthreads();

        // every thread sums the 8 partials in identical order -> identical S
        float S = red_sum[it & 1][0];
        #pragma unroll
        for (int j = 1; j < NWARP; j++) S += red_sum[it & 1][j];

        float inv = rcpf(S);
        u64 inv2 = pk2(inv, inv);

        #pragma unroll
        for (int p = 0; p < NPAIR; p++) {
            u64 oh = mul2(w2[p], inv2);          // onehot = w / S
            k2[p]  = add2(k2[p], oh);            // khot += onehot
            u64 t  = fma2(oh, NONE2, ONE2);      // t = 1 - onehot
            float tl, th; upk2(t, tl, th);
            tl = fmaxf(tl, EPSF); th = fmaxf(th, EPSF);   // alu pipe, overlapped
            t = pk2(tl, th);
            w2[p] = mul2(w2[p], t);              // w *= mask
        }
    }

    // ---- store khot (coalesced float4) ----
    float4* o4 = reinterpret_cast<float4*>(out + base);
    #pragma unroll
    for (int j = 0; j < 4; j++) {
        float4 v;
        upk2(k2[2*j],     v.x, v.y);
        upk2(k2[2*j + 1], v.z, v.w);
        o4[j * TPB + tid] = v;
    }
}

extern "C" void kernel_launch(void* const* d_in, const int* in_sizes, int n_in,
                              void* d_out, int out_size) {
    const float* scores = (const float*)d_in[0];
    const float* g      = (const float*)d_in[1];
    float* out          = (float*)d_out;
    int rows = in_sizes[0] / NCOL;   // 4*2048 = 8192
    subset_op_kernel<<<rows, TPB>>>(scores, g, out);
}

// round 4
// speedup vs baseline: 1.1712x; 1.1712x over previous
#include <cuda_runtime.h>

typedef unsigned long long u64;

#define TPB   256
#define NCOL  4096
#define VPT   16      // values per thread
#define NPAIR 8
#define NWARP 8
#define KITER 16

// ---- packed f32x2 helpers (ptxas never auto-fuses these from C++) ----
__device__ __forceinline__ u64 pk2(float a, float b) {
    u64 r; asm("mov.b64 %0,{%1,%2};" : "=l"(r) : "f"(a), "f"(b)); return r;
}
__device__ __forceinline__ void upk2(u64 v, float& a, float& b) {
    asm("mov.b64 {%0,%1},%2;" : "=f"(a), "=f"(b) : "l"(v));
}
__device__ __forceinline__ u64 mul2(u64 a, u64 b) {
    u64 d; asm("mul.rn.f32x2 %0,%1,%2;" : "=l"(d) : "l"(a), "l"(b)); return d;
}
__device__ __forceinline__ u64 add2(u64 a, u64 b) {
    u64 d; asm("add.rn.f32x2 %0,%1,%2;" : "=l"(d) : "l"(a), "l"(b)); return d;
}
__device__ __forceinline__ u64 fma2(u64 a, u64 b, u64 c) {
    u64 d; asm("fma.rn.f32x2 %0,%1,%2,%3;" : "=l"(d) : "l"(a), "l"(b), "l"(c)); return d;
}
__device__ __forceinline__ float rcpf(float x) {
    float r; asm("rcp.approx.f32 %0,%1;" : "=f"(r) : "f"(x)); return r;
}

// One CTA per row of 4096. w = exp(s - max) in registers (8 f32x2 pairs),
// khot accumulated in registers. Per iteration:
//   S = block_sum(w); ninv = -1/S
//   noh = w * ninv          (= -onehot)
//   k   = fma(noh, -1, k)   (khot += onehot)
//   w   = fma(noh, w, w)    (w *= 1 - onehot)
// 3 packed fma-pipe ops per pair per iteration; no clamp (rcp overshoot makes
// w at worst ~ -1e-7*S, whose later contributions are ~1e-7 << 1e-3 gate).
// Last iteration's w update is dead and peeled off.
__global__ __launch_bounds__(TPB, 5) void subset_op_kernel(
    const float* __restrict__ scores, const float* __restrict__ g,
    float* __restrict__ out)
{
    __shared__ float red_max[NWARP];
    __shared__ __align__(16) float red_sum[2][NWARP];

    const int tid  = threadIdx.x;
    const int lane = tid & 31;
    const int wid  = tid >> 5;
    const size_t base = (size_t)blockIdx.x * NCOL;

    const float4* sc4 = reinterpret_cast<const float4*>(scores + base);
    const float4* g4  = reinterpret_cast<const float4*>(g + base);

    // ---- load + perturb: s = scores + g (coalesced float4) ----
    float s[VPT];
    #pragma unroll
    for (int j = 0; j < 4; j++) {
        float4 a = sc4[j * TPB + tid];
        float4 b = g4 [j * TPB + tid];
        s[4*j+0] = a.x + b.x; s[4*j+1] = a.y + b.y;
        s[4*j+2] = a.z + b.z; s[4*j+3] = a.w + b.w;
    }

    // ---- block max (one-time) ----
    float m = s[0];
    #pragma unroll
    for (int i = 1; i < VPT; i++) m = fmaxf(m, s[i]);
    #pragma unroll
    for (int o = 16; o > 0; o >>= 1)
        m = fmaxf(m, __shfl_xor_sync(0xffffffffu, m, o));
    if (lane == 0) red_max[wid] = m;
    __syncthreads();
    #pragma unroll
    for (int j = 0; j < NWARP; j++) m = fmaxf(m, red_max[j]);   // broadcast, identical in all threads

    // ---- w = exp(s - m): the ONLY transcendental ----
    u64 w2[NPAIR], k2[NPAIR];
    #pragma unroll
    for (int p = 0; p < NPAIR; p++) {
        w2[p] = pk2(__expf(s[2*p] - m), __expf(s[2*p+1] - m));
        k2[p] = pk2(0.f, 0.f);
    }

    const u64 NONE2 = pk2(-1.f, -1.f);

    // ---- block sum of w -> ninv2 = {-1/S, -1/S}; 1 barrier per iteration ----
    auto block_ninv = [&](int it) -> u64 {
        u64 a0 = add2(w2[0], w2[1]);
        u64 a1 = add2(w2[2], w2[3]);
        u64 a2 = add2(w2[4], w2[5]);
        u64 a3 = add2(w2[6], w2[7]);
        a0 = add2(a0, a1); a2 = add2(a2, a3);
        a0 = add2(a0, a2);
        float lo, hi; upk2(a0, lo, hi);
        float local = lo + hi;
        #pragma unroll
        for (int o = 16; o > 0; o >>= 1)
            local += __shfl_xor_sync(0xffffffffu, local, o);
        if (lane == 0) red_sum[it & 1][wid] = local;
        __syncthreads();
        // broadcast read of the 8 partials as two float4, packed-summed
        float4 r0 = *reinterpret_cast<const float4*>(&red_sum[it & 1][0]);
        float4 r1 = *reinterpret_cast<const float4*>(&red_sum[it & 1][4]);
        u64 t0 = add2(pk2(r0.x, r0.y), pk2(r0.z, r0.w));
        u64 t1 = add2(pk2(r1.x, r1.y), pk2(r1.z, r1.w));
        t0 = add2(t0, t1);
        float sl, sh; upk2(t0, sl, sh);
        float ninv = rcpf(sl + sh);
        return pk2(-ninv, -ninv);
    };

    for (int it = 0; it < KITER - 1; it++) {
        u64 ninv2 = block_ninv(it);
        #pragma unroll
        for (int p = 0; p < NPAIR; p++) {
            u64 noh = mul2(w2[p], ninv2);        // -onehot
            k2[p]   = fma2(noh, NONE2, k2[p]);   // khot += onehot
            w2[p]   = fma2(noh, w2[p], w2[p]);   // w *= (1 - onehot)
        }
    }
    {   // last iteration: w update is dead
        u64 ninv2 = block_ninv(KITER - 1);
        #pragma unroll
        for (int p = 0; p < NPAIR; p++) {
            u64 noh = mul2(w2[p], ninv2);
            k2[p]   = fma2(noh, NONE2, k2[p]);
        }
    }

    // ---- store khot (coalesced float4) ----
    float4* o4 = reinterpret_cast<float4*>(out + base);
    #pragma unroll
    for (int j = 0; j < 4; j++) {
        float4 v;
        upk2(k2[2*j],     v.x, v.y);
        upk2(k2[2*j + 1], v.z, v.w);
        o4[j * TPB + tid] = v;
    }
}

extern "C" void kernel_launch(void* const* d_in, const int* in_sizes, int n_in,
                              void* d_out, int out_size) {
    const float* scores = (const float*)d_in[0];
    const float* g      = (const float*)d_in[1];
    float* out          = (float*)d_out;
    int rows = in_sizes[0] / NCOL;   // 4*2048 = 8192
    subset_op_kernel<<<rows, TPB>>>(scores, g, out);
}